// round 13
// baseline (speedup 1.0000x reference)
#include <cuda_runtime.h>
#include <math.h>

#define K_TOP 512
#define CAP 4096

// level dims
#define D1 48
#define H1 96
#define W1 96
#define NV1 (D1*H1*W1)   // 442368
#define D2 24
#define H2 48
#define W2 48
#define NV2 (D2*H2*W2)   // 55296
#define D3 12
#define H3 24
#define W3 24
#define NV3 (D3*H3*W3)   // 6912

typedef unsigned long long u64;

// ------------------------------------------------------------------
// packed f32x2 primitives (sm_103a FFMA2 path)
// ------------------------------------------------------------------
__device__ __forceinline__ u64 bcast2(float a){
  u64 r; asm("mov.b64 %0, {%1, %1};" : "=l"(r) : "f"(a)); return r;
}
__device__ __forceinline__ void unpack2(u64 v, float& lo, float& hi){
  asm("mov.b64 {%0, %1}, %2;" : "=f"(lo), "=f"(hi) : "l"(v));
}
__device__ __forceinline__ u64 fma2(u64 a, u64 b, u64 c){
  u64 r; asm("fma.rn.f32x2 %0, %1, %2, %3;" : "=l"(r) : "l"(a), "l"(b), "l"(c)); return r;
}
__device__ __forceinline__ u64 add2(u64 a, u64 b){
  u64 r; asm("add.rn.f32x2 %0, %1, %2;" : "=l"(r) : "l"(a), "l"(b)); return r;
}

#define NEG2 0xBF800000BF800000ULL   // {-1.f,-1.f}
#define MZ2  0x8000000080000000ULL   // {-0.f,-0.f}

// Kahan-fold of a group value g into (s, cn) with cn = -c. 4 ops.
__device__ __forceinline__ void kfold2(u64& s, u64& cn, u64 g){
  u64 y = add2(g, cn);
  u64 t = add2(s, y);
  u64 z = fma2(t, NEG2, s);     // RN(s - t)
  cn = add2(y, z);
  s = t;
}
__device__ __forceinline__ u64 kfin2(u64 s, u64 cn){ return add2(s, cn); }  // s - c

// ------------------------------------------------------------------
// scratch (static __device__, no runtime allocation)
// ------------------------------------------------------------------
__device__ float g_f1[16*NV1];
__device__ float g_f2[32*NV2];
__device__ float g_f3[64*NV3];
__device__ float g_p1[32*NV1];
__device__ float g_p2[32*NV2];
__device__ float g_p3[32*NV3];
__device__ float g_s1[NV1];
__device__ float g_s2[NV2];
__device__ float g_s3[NV3];
__device__ float g_c1t[432];      // [k27][o16]
__device__ float g_c2t[13824];    // [k27][ci16][o32]
__device__ float g_c3t[55296];    // [k27][ci32][o64]
__device__ float g_l1t[512];      // [ci16][c32]
__device__ float g_l2t[1024];     // [ci32][c32]
__device__ float g_l3t[2048];     // [ci64][c32]
__device__ unsigned g_hist16[3][65536];
__device__ unsigned g_hist8[3][256];
__device__ int g_ctrl[3][8];
__device__ unsigned g_candKey[3][CAP];
__device__ unsigned g_candIdx[3][CAP];
__device__ float g_topval[3*K_TOP];
__device__ unsigned g_topidx[3*K_TOP];

// ------------------------------------------------------------------
__global__ void prep_k(const float* __restrict__ c1w, const float* __restrict__ c2w,
                       const float* __restrict__ c3w, const float* __restrict__ l1w,
                       const float* __restrict__ l2w, const float* __restrict__ l3w){
  int t = blockIdx.x*blockDim.x + threadIdx.x;
  if (t < 432){ int k=t/16, o=t%16; g_c1t[t] = c1w[o*27+k]; }
  if (t < 13824){ int k=t/512; int ci=(t>>5)&15; int o=t&31; g_c2t[t]=c2w[(o*16+ci)*27+k]; }
  if (t < 55296){ int k=t/2048; int ci=(t>>6)&31; int o=t&63; g_c3t[t]=c3w[(o*32+ci)*27+k]; }
  if (t < 512){ int ci=t/32, c=t%32; g_l1t[t]=l1w[c*16+ci]; }
  if (t < 1024){ int ci=t/32, c=t%32; g_l2t[t]=l2w[c*32+ci]; }
  if (t < 2048){ int ci=t/32, c=t%32; g_l3t[t]=l3w[c*64+ci]; }
}

// ------------------------------------------------------------------
// conv1: [1,96,192,192] -> relu -> f1 [16,48,96,96], 3x3x3 s2 SAME
// grouped Kahan over taps (7 groups of 4, tap 27 zero-padded)
// ------------------------------------------------------------------
__global__ void conv1_k(const float* __restrict__ x, const float* __restrict__ b){
  __shared__ float ws[448];    // [k28][o16], taps 27 padded with zeros
  __shared__ float bs[16];
  int tid = threadIdx.x;
  if (tid < 108) ((float4*)ws)[tid] = ((const float4*)g_c1t)[tid];
  if (tid >= 108 && tid < 112) ((float4*)ws)[tid] = make_float4(0.f,0.f,0.f,0.f);
  if (tid < 16) bs[tid] = b[tid];
  __syncthreads();
  const u64* wsu = (const u64*)ws;
  int v = blockIdx.x*256 + tid;
  int z = v / (H1*W1); int r = v % (H1*W1); int y = r / W1; int xx = r % W1;
  u64 S[8], C[8];
#pragma unroll
  for (int j=0;j<8;j++){ S[j]=0ULL; C[j]=MZ2; }
#pragma unroll
  for (int kk=0;kk<28;kk+=4){
    u64 in[4];
#pragma unroll
    for (int q=0;q<4;q++){
      int k=kk+q;
      float val=0.f;
      if (k<27){
        int kd=k/9, kh=(k%9)/3, kw=k%3;
        int iz=2*z+kd, iy=2*y+kh, ix=2*xx+kw;
        if (iz<96 && iy<192 && ix<192) val=__ldg(&x[(iz*192+iy)*192+ix]);
      }
      in[q]=bcast2(val);
    }
#pragma unroll
    for (int j=0;j<8;j++){
      u64 g = fma2(in[0], wsu[(kk  )*8+j], MZ2);
      g = fma2(in[1], wsu[(kk+1)*8+j], g);
      g = fma2(in[2], wsu[(kk+2)*8+j], g);
      g = fma2(in[3], wsu[(kk+3)*8+j], g);
      kfold2(S[j],C[j],g);
    }
  }
#pragma unroll
  for (int j=0;j<8;j++){
    float v0,v1; unpack2(kfin2(S[j],C[j]),v0,v1);
    g_f1[(2*j  )*NV1+v] = fmaxf(__fadd_rn(v0,bs[2*j  ]),0.f);
    g_f1[(2*j+1)*NV1+v] = fmaxf(__fadd_rn(v1,bs[2*j+1]),0.f);
  }
}

// ------------------------------------------------------------------
// conv2: f1 [16,48,96,96] -> relu -> f2 [32,24,48,48]
// Shared-memory input tiling: block = 1z x 8y x 8x output tile,
// ALL 32 oc (64 voxels x 4 og of 8oc = 256 threads). f1 tile + weights
// staged in 2 phases of 8 ci. No oc-split redundancy, no LDG in loop.
// ------------------------------------------------------------------
__global__ void conv2_k(const float* __restrict__ b){
  __shared__ float shin[6936];  // [ci8][z3][y17][x17]  (867 per ci)
  __shared__ float ws[6912];    // [k27][ci8][o32]
  int tid=threadIdx.x;
  int bt=blockIdx.x;            // 864 = 24z * 6ty * 6tx
  int z0=bt/36; int rem=bt%36; int ty=rem/6; int tx=rem%6;
  int og=tid&3; int vi=tid>>2;  // vi 0..63
  int ly=vi>>3, lx=vi&7;
  int iy0=ty*16, ix0=tx*16, iz0=2*z0;
  u64 S[4], C[4];
#pragma unroll
  for(int j=0;j<4;j++){ S[j]=0ULL; C[j]=MZ2; }
  const u64* wsu=(const u64*)ws;
  for(int ph=0; ph<2; ph++){
    __syncthreads();
    for(int i=tid;i<6936;i+=256){
      int ci=i/867; int r=i%867; int lz=r/289; int r2=r%289; int lyy=r2/17; int lxx=r2%17;
      int gz=iz0+lz, gy=iy0+lyy, gx=ix0+lxx;
      shin[i]=(gz<D1&&gy<H1&&gx<W1)? g_f1[(ph*8+ci)*NV1+(gz*H1+gy)*W1+gx] : 0.f;
    }
    for(int i=tid;i<6912;i+=256){
      int k=i>>8; int r=i&255; int ci=r>>5; int o=r&31;
      ws[i]=g_c2t[k*512+(ph*8+ci)*32+o];
    }
    __syncthreads();
#pragma unroll
    for(int kd=0;kd<3;kd++){
#pragma unroll
      for(int kh=0;kh<3;kh++){
#pragma unroll
        for(int kw=0;kw<3;kw++){
          int kl=(kd*3+kh)*3+kw;
          const float* sin=&shin[kd*289+(2*ly+kh)*17+(2*lx+kw)];
          const u64* wk=&wsu[kl*128 + og*4];
#pragma unroll
          for(int cg=0;cg<2;cg++){
            int ci0=cg*4;
            u64 in0=bcast2(sin[(ci0  )*867]);
            u64 in1=bcast2(sin[(ci0+1)*867]);
            u64 in2=bcast2(sin[(ci0+2)*867]);
            u64 in3=bcast2(sin[(ci0+3)*867]);
#pragma unroll
            for(int j=0;j<4;j++){
              u64 g = fma2(in0, wk[(ci0  )*16+j], MZ2);
              g = fma2(in1, wk[(ci0+1)*16+j], g);
              g = fma2(in2, wk[(ci0+2)*16+j], g);
              g = fma2(in3, wk[(ci0+3)*16+j], g);
              kfold2(S[j],C[j],g);
            }
          }
        }
      }
    }
  }
  int y=ty*8+ly, xx=tx*8+lx;
  int v=(z0*H2+y)*W2+xx;
#pragma unroll
  for(int j=0;j<4;j++){
    float v0,v1; unpack2(kfin2(S[j],C[j]),v0,v1);
    int c=og*8+2*j;
    g_f2[c*NV2+v]    =fmaxf(__fadd_rn(v0,__ldg(&b[c])),0.f);
    g_f2[(c+1)*NV2+v]=fmaxf(__fadd_rn(v1,__ldg(&b[c+1])),0.f);
  }
}

// ------------------------------------------------------------------
// conv3: f2 -> relu -> f3; balanced warp layout; grouped Kahan (8x4 ci)
// ------------------------------------------------------------------
__global__ void conv3_k(const float* __restrict__ b){
  __shared__ float ws[8192];    // 4 taps * 32ci * 64oc
  __shared__ float shin[7200];  // 32ci * 5*5*9
  int tid=threadIdx.x;          // 256 threads
  int bt=blockIdx.x;
  int btz=bt/72; int rem=bt%72; int bty=rem/6; int btx=rem%6;
  int og = ((tid>>2)&7) | (((tid>>5)&1)<<3);   // 0..15 (4 oc each)
  int vi = (tid&3) | (((tid>>6)&3)<<2);        // 0..15
  int vz=vi>>3; int vy=(vi>>2)&1; int vx=vi&3;
  int z0=btz*4, y0=bty*4, x0=btx*8;
  for(int i=tid;i<7200;i+=256){
    int cl=i/225; int r=i%225; int lz=r/45; int r2=r%45; int ly=r2/9; int lx=r2%9;
    int gz=z0+lz, gy=y0+ly, gx=x0+lx;
    shin[i]=(gz<D2&&gy<H2&&gx<W2)? g_f2[cl*NV2+(gz*H2+gy)*W2+gx] : 0.f;
  }
  const u64* wsu=(const u64*)ws;
  u64 S[2]={0ULL,0ULL}, C[2]={MZ2,MZ2};
  int sbase=(2*vz)*45+(2*vy)*9+(2*vx);
  for(int ph=0; ph<7; ph++){
    int ktaps=(ph==6)?3:4;
    __syncthreads();
    for(int i=tid;i<ktaps*2048;i+=256) ws[i]=g_c3t[ph*8192+i];
    __syncthreads();
    for(int kl=0;kl<ktaps;kl++){
      int k=ph*4+kl;
      int kd=k/9, kh=(k%9)/3, kw=k%3;
      const float* sh=&shin[sbase + kd*45 + kh*9 + kw];
      const u64* wb=&wsu[kl*1024 + og*2];
#pragma unroll
      for(int cg=0;cg<8;cg++){
        int ci0=cg*4;
        u64 in0=bcast2(sh[(ci0  )*225]);
        u64 in1=bcast2(sh[(ci0+1)*225]);
        u64 in2=bcast2(sh[(ci0+2)*225]);
        u64 in3=bcast2(sh[(ci0+3)*225]);
        u64 g0 = fma2(in0, wb[(ci0  )*32], MZ2);
        u64 g1 = fma2(in0, wb[(ci0  )*32+1], MZ2);
        g0 = fma2(in1, wb[(ci0+1)*32], g0);
        g1 = fma2(in1, wb[(ci0+1)*32+1], g1);
        g0 = fma2(in2, wb[(ci0+2)*32], g0);
        g1 = fma2(in2, wb[(ci0+2)*32+1], g1);
        g0 = fma2(in3, wb[(ci0+3)*32], g0);
        g1 = fma2(in3, wb[(ci0+3)*32+1], g1);
        kfold2(S[0],C[0],g0);
        kfold2(S[1],C[1],g1);
      }
    }
  }
  int oz=btz*2+vz, oy=bty*2+vy, ox=btx*4+vx;
  int v=(oz*H3+oy)*W3+ox;
#pragma unroll
  for(int j=0;j<2;j++){
    float v0,v1; unpack2(kfin2(S[j],C[j]),v0,v1);
    int c=og*4+2*j;
    g_f3[c*NV3+v]    =fmaxf(__fadd_rn(v0,__ldg(&b[c])),0.f);
    g_f3[(c+1)*NV3+v]=fmaxf(__fadd_rn(v1,__ldg(&b[c+1])),0.f);
  }
}

// ------------------------------------------------------------------
__device__ __forceinline__ unsigned okey(float f){
  unsigned u=__float_as_uint(f);
  return (u & 0x80000000u) ? ~u : (u | 0x80000000u);
}
__device__ __forceinline__ float fromkey(unsigned k){
  unsigned u = (k & 0x80000000u) ? (k ^ 0x80000000u) : ~k;
  return __uint_as_float(u);
}

// ------------------------------------------------------------------
// FPN laterals + top-down adds + channel-max score (+ fused hist16)
// ------------------------------------------------------------------
__global__ void p3_k(const float* __restrict__ b){
  __shared__ float lw[2048];
  int tid=threadIdx.x;
  for(int i=tid;i<512;i+=256) ((float4*)lw)[i]=((const float4*)g_l3t)[i];
  __syncthreads();
  const u64* lwu=(const u64*)lw;
  int v=blockIdx.x*256+tid;
  u64 S[16], C[16];
#pragma unroll
  for(int j=0;j<16;j++){ S[j]=0ULL; C[j]=MZ2; }
#pragma unroll 4
  for(int cg=0;cg<16;cg++){
    int ci0=cg*4;
    u64 in0=bcast2(g_f3[(ci0  )*NV3+v]);
    u64 in1=bcast2(g_f3[(ci0+1)*NV3+v]);
    u64 in2=bcast2(g_f3[(ci0+2)*NV3+v]);
    u64 in3=bcast2(g_f3[(ci0+3)*NV3+v]);
#pragma unroll
    for(int j=0;j<16;j++){
      u64 g = fma2(in0, lwu[(ci0  )*16+j], MZ2);
      g = fma2(in1, lwu[(ci0+1)*16+j], g);
      g = fma2(in2, lwu[(ci0+2)*16+j], g);
      g = fma2(in3, lwu[(ci0+3)*16+j], g);
      kfold2(S[j],C[j],g);
    }
  }
  float mx=-1e30f;
#pragma unroll
  for(int j=0;j<16;j++){
    float v0,v1; unpack2(kfin2(S[j],C[j]),v0,v1);
    float p0=__fadd_rn(v0,__ldg(&b[2*j]));
    float p1=__fadd_rn(v1,__ldg(&b[2*j+1]));
    g_p3[(2*j)*NV3+v]=p0; g_p3[(2*j+1)*NV3+v]=p1;
    mx=fmaxf(mx,fmaxf(p0,p1));
  }
  g_s3[v]=mx;
  atomicAdd(&g_hist16[2][okey(mx)>>16],1u);
}

__global__ void p2_k(const float* __restrict__ b){
  __shared__ float lw[1024];
  int tid=threadIdx.x;
  if(tid<256) ((float4*)lw)[tid]=((const float4*)g_l2t)[tid];
  __syncthreads();
  const u64* lwu=(const u64*)lw;
  int v=blockIdx.x*256+tid;
  int z=v/(H2*W2); int r=v%(H2*W2); int y=r/W2; int xx=r%W2;
  int v3=((z>>1)*H3+(y>>1))*W3+(xx>>1);
  u64 S[16], C[16];
#pragma unroll
  for(int j=0;j<16;j++){ S[j]=0ULL; C[j]=MZ2; }
#pragma unroll 2
  for(int cg=0;cg<8;cg++){
    int ci0=cg*4;
    u64 in0=bcast2(g_f2[(ci0  )*NV2+v]);
    u64 in1=bcast2(g_f2[(ci0+1)*NV2+v]);
    u64 in2=bcast2(g_f2[(ci0+2)*NV2+v]);
    u64 in3=bcast2(g_f2[(ci0+3)*NV2+v]);
#pragma unroll
    for(int j=0;j<16;j++){
      u64 g = fma2(in0, lwu[(ci0  )*16+j], MZ2);
      g = fma2(in1, lwu[(ci0+1)*16+j], g);
      g = fma2(in2, lwu[(ci0+2)*16+j], g);
      g = fma2(in3, lwu[(ci0+3)*16+j], g);
      kfold2(S[j],C[j],g);
    }
  }
  float mx=-1e30f;
#pragma unroll
  for(int j=0;j<16;j++){
    float v0,v1; unpack2(kfin2(S[j],C[j]),v0,v1);
    float p0=__fadd_rn(__fadd_rn(v0,__ldg(&b[2*j])),   g_p3[(2*j)*NV3+v3]);
    float p1=__fadd_rn(__fadd_rn(v1,__ldg(&b[2*j+1])), g_p3[(2*j+1)*NV3+v3]);
    g_p2[(2*j)*NV2+v]=p0; g_p2[(2*j+1)*NV2+v]=p1;
    mx=fmaxf(mx,fmaxf(p0,p1));
  }
  g_s2[v]=mx;
  atomicAdd(&g_hist16[1][okey(mx)>>16],1u);
}

__global__ void p1_k(const float* __restrict__ b){
  __shared__ float lw[512];
  int tid=threadIdx.x;
  if(tid<128) ((float4*)lw)[tid]=((const float4*)g_l1t)[tid];
  __syncthreads();
  const u64* lwu=(const u64*)lw;
  int v=blockIdx.x*256+tid;
  int z=v/(H1*W1); int r=v%(H1*W1); int y=r/W1; int xx=r%W1;
  int v2=((z>>1)*H2+(y>>1))*W2+(xx>>1);
  u64 S[16], C[16];
#pragma unroll
  for(int j=0;j<16;j++){ S[j]=0ULL; C[j]=MZ2; }
#pragma unroll
  for(int cg=0;cg<4;cg++){
    int ci0=cg*4;
    u64 in0=bcast2(g_f1[(ci0  )*NV1+v]);
    u64 in1=bcast2(g_f1[(ci0+1)*NV1+v]);
    u64 in2=bcast2(g_f1[(ci0+2)*NV1+v]);
    u64 in3=bcast2(g_f1[(ci0+3)*NV1+v]);
#pragma unroll
    for(int j=0;j<16;j++){
      u64 g = fma2(in0, lwu[(ci0  )*16+j], MZ2);
      g = fma2(in1, lwu[(ci0+1)*16+j], g);
      g = fma2(in2, lwu[(ci0+2)*16+j], g);
      g = fma2(in3, lwu[(ci0+3)*16+j], g);
      kfold2(S[j],C[j],g);
    }
  }
  float mx=-1e30f;
#pragma unroll
  for(int j=0;j<16;j++){
    float v0,v1; unpack2(kfin2(S[j],C[j]),v0,v1);
    float p0=__fadd_rn(__fadd_rn(v0,__ldg(&b[2*j])),   g_p2[(2*j)*NV2+v2]);
    float p1=__fadd_rn(__fadd_rn(v1,__ldg(&b[2*j+1])), g_p2[(2*j+1)*NV2+v2]);
    g_p1[(2*j)*NV1+v]=p0; g_p1[(2*j+1)*NV1+v]=p1;
    mx=fmaxf(mx,fmaxf(p0,p1));
  }
  g_s1[v]=mx;
  atomicAdd(&g_hist16[0][okey(mx)>>16],1u);
}

// ------------------------------------------------------------------
// exact top-K=512 per level
// ------------------------------------------------------------------
__device__ __forceinline__ const float* level_score(int l){
  return (l==0)? g_s1 : (l==1)? g_s2 : g_s3;
}
__device__ __forceinline__ int level_n(int l){
  return (l==0)? NV1 : (l==1)? NV2 : NV3;
}

__global__ void tk_clear(){
  int t=blockIdx.x*256+threadIdx.x;
  if(t<3*65536) ((unsigned*)g_hist16)[t]=0;
  if(t<3*256) ((unsigned*)g_hist8)[t]=0;
  if(t<3*8) ((int*)g_ctrl)[t]=0;
}
__global__ void tk_find16(){
  int l=blockIdx.x;
  __shared__ unsigned part[256];
  int t=threadIdx.x;
  unsigned sm=0;
  for(int i=0;i<256;i++) sm+=g_hist16[l][t*256+i];
  part[t]=sm;
  __syncthreads();
  if(t==0){
    unsigned cum=0;
    for(int c=255;c>=0;c--){
      if(cum+part[c]>=K_TOP){
        for(int bb=c*256+255;;bb--){
          unsigned h=g_hist16[l][bb];
          if(cum+h>=K_TOP){ g_ctrl[l][0]=bb; g_ctrl[l][1]=(int)cum; break; }
          cum+=h;
        }
        break;
      }
      cum+=part[c];
    }
  }
}
__global__ void tk_hist8(){
  int l=blockIdx.y;
  int t=blockIdx.x*256+threadIdx.x; if(t>=level_n(l))return;
  unsigned k=okey(level_score(l)[t]);
  if((int)(k>>16)==g_ctrl[l][0]) atomicAdd(&g_hist8[l][(k>>8)&255],1u);
}
__global__ void tk_find8(){
  int l=threadIdx.x; if(l>=3)return;
  unsigned cum=(unsigned)g_ctrl[l][1];
  int b16=g_ctrl[l][0];
  for(int bb=255;bb>=0;bb--){
    unsigned h=g_hist8[l][bb];
    if(cum+h>=K_TOP){ g_ctrl[l][2]=(b16<<8)|bb; break; }
    cum+=h;
  }
}
__global__ void tk_gather(){
  int l=blockIdx.y;
  int t=blockIdx.x*256+threadIdx.x; if(t>=level_n(l))return;
  unsigned k=okey(level_score(l)[t]);
  if((int)(k>>8) >= g_ctrl[l][2]){
    int pos=atomicAdd(&g_ctrl[l][3],1);
    if(pos<CAP){ g_candKey[l][pos]=k; g_candIdx[l][pos]=t; }
  }
}
__global__ void tk_sort(){
  int level=blockIdx.x;
  __shared__ unsigned long long a[CAP];
  int t=threadIdx.x;
  int M=min(g_ctrl[level][3],CAP);
  for(int i=t;i<CAP;i+=1024)
    a[i] = (i<M)? ((((unsigned long long)g_candKey[level][i])<<32) | (unsigned)(~g_candIdx[level][i])) : 0ULL;
  __syncthreads();
  for(int kk=2;kk<=CAP;kk<<=1){
    for(int j=kk>>1;j>0;j>>=1){
      for(int i=t;i<CAP;i+=1024){
        int ixj=i^j;
        if(ixj>i){
          bool asc=((i&kk)!=0);
          unsigned long long A=a[i],B=a[ixj];
          if(asc? (A>B):(A<B)){ a[i]=B; a[ixj]=A; }
        }
      }
      __syncthreads();
    }
  }
  if(t<K_TOP){
    unsigned long long c=a[t];
    g_topval[level*K_TOP+t]=fromkey((unsigned)(c>>32));
    g_topidx[level*K_TOP+t]=~((unsigned)c);
  }
}

// ------------------------------------------------------------------
// per-candidate: cube mean/std (fp64, parallel gather) -> MLP -> out
// ------------------------------------------------------------------
__global__ void mlp_k(const float* __restrict__ w1,const float* __restrict__ b1,
                      const float* __restrict__ w2,const float* __restrict__ b2,
                      float* __restrict__ out){
  int l=blockIdx.y; int slot=blockIdx.x; int t=threadIdx.x;
  __shared__ float cvs[2048];    // [ch32][64]
  __shared__ double psum[128];
  __shared__ double msh[32];
  __shared__ float feat[64];
  __shared__ float h[128];
  int D,H,W; const float* p;
  if(l==0){D=D1;H=H1;W=W1;p=g_p1;}
  else if(l==1){D=D2;H=H2;W=W2;p=g_p2;}
  else {D=D3;H=H3;W=W3;p=g_p3;}
  unsigned idx=g_topidx[l*K_TOP+slot];
  float val=g_topval[l*K_TOP+slot];
  int plane=D*H*W;
  int z=(int)idx/(H*W); int r=(int)idx%(H*W); int y=r/W; int xx=r%W;
  int zs=min(max(z-2,0),D-4);
  int ys=min(max(y-2,0),H-4);
  int xs=min(max(xx-2,0),W-4);
  int ch=t>>2, part=t&3;
  {
    const float* base = p + ch*plane + ((zs+part)*H+ys)*W + xs;
    float* cvp = &cvs[ch*64 + part*16];
    double s=0.0;
#pragma unroll
    for(int dy=0;dy<4;dy++)
#pragma unroll
      for(int dx=0;dx<4;dx++){
        float vv = base[dy*W+dx];
        cvp[dy*4+dx]=vv;
        s += (double)vv;
      }
    psum[t]=s;
  }
  __syncthreads();
  if(t<32){
    double m=(((psum[t*4]+psum[t*4+1])+psum[t*4+2])+psum[t*4+3])*(1.0/64.0);
    msh[t]=m;
    feat[t]=(float)m;
  }
  __syncthreads();
  {
    double m=msh[ch];
    const float* cvp=&cvs[ch*64 + part*16];
    double ss=0.0;
#pragma unroll
    for(int k=0;k<16;k++){ double d=(double)cvp[k]-m; ss+=d*d; }
    psum[t]=ss;
  }
  __syncthreads();
  if(t<32){
    double var=(((psum[t*4]+psum[t*4+1])+psum[t*4+2])+psum[t*4+3])*(1.0/64.0);
    feat[32+t]=(float)sqrt(var+1e-6);
  }
  __syncthreads();
  {
    double acc=0.0;
    for(int i=0;i<64;i++) acc += (double)feat[i]*(double)__ldg(&w1[i*128+t]);
    h[t]=fmaxf((float)(acc+(double)__ldg(&b1[t])),0.f);
  }
  __syncthreads();
  if(t<2){
    double acc=0.0;
    for(int j=0;j<128;j++) acc+=(double)h[j]*(double)__ldg(&w2[j*2+t]);
    float valid=(val>0.5f)?1.f:0.f;
    out[(l*K_TOP+slot)*2+t]=(float)(acc+(double)__ldg(&b2[t]))*valid;
  }
}

// ------------------------------------------------------------------
extern "C" void kernel_launch(void* const* d_in, const int* in_sizes, int n_in,
                              void* d_out, int out_size){
  const float* x  =(const float*)d_in[0];
  const float* c1w=(const float*)d_in[1];  const float* c1b=(const float*)d_in[2];
  const float* c2w=(const float*)d_in[3];  const float* c2b=(const float*)d_in[4];
  const float* c3w=(const float*)d_in[5];  const float* c3b=(const float*)d_in[6];
  const float* l1w=(const float*)d_in[7];  const float* l1b=(const float*)d_in[8];
  const float* l2w=(const float*)d_in[9];  const float* l2b=(const float*)d_in[10];
  const float* l3w=(const float*)d_in[11]; const float* l3b=(const float*)d_in[12];
  const float* w1 =(const float*)d_in[13]; const float* b1 =(const float*)d_in[14];
  const float* w2 =(const float*)d_in[15]; const float* b2 =(const float*)d_in[16];
  float* out=(float*)d_out;

  prep_k<<<216,256>>>(c1w,c2w,c3w,l1w,l2w,l3w);
  tk_clear<<<768,256>>>();
  conv1_k<<<NV1/256,256>>>(x,c1b);
  conv2_k<<<864,256>>>(c2b);
  conv3_k<<<432,256>>>(c3b);
  p3_k<<<NV3/256,256>>>(l3b);
  p2_k<<<NV2/256,256>>>(l2b);
  p1_k<<<NV1/256,256>>>(l1b);

  int nb=(NV1+255)/256;
  tk_find16<<<3,256>>>();
  tk_hist8<<<dim3(nb,3),256>>>();
  tk_find8<<<1,32>>>();
  tk_gather<<<dim3(nb,3),256>>>();
  tk_sort<<<3,1024>>>();

  mlp_k<<<dim3(K_TOP,3),128>>>(w1,b1,w2,b2,out);
}

// round 14
// speedup vs baseline: 1.0941x; 1.0941x over previous
#include <cuda_runtime.h>
#include <math.h>

#define K_TOP 512
#define CAP 4096

// level dims
#define D1 48
#define H1 96
#define W1 96
#define NV1 (D1*H1*W1)   // 442368
#define D2 24
#define H2 48
#define W2 48
#define NV2 (D2*H2*W2)   // 55296
#define D3 12
#define H3 24
#define W3 24
#define NV3 (D3*H3*W3)   // 6912

typedef unsigned long long u64;

// ------------------------------------------------------------------
// packed f32x2 primitives (sm_103a FFMA2 path)
// ------------------------------------------------------------------
__device__ __forceinline__ u64 bcast2(float a){
  u64 r; asm("mov.b64 %0, {%1, %1};" : "=l"(r) : "f"(a)); return r;
}
__device__ __forceinline__ void unpack2(u64 v, float& lo, float& hi){
  asm("mov.b64 {%0, %1}, %2;" : "=f"(lo), "=f"(hi) : "l"(v));
}
__device__ __forceinline__ u64 fma2(u64 a, u64 b, u64 c){
  u64 r; asm("fma.rn.f32x2 %0, %1, %2, %3;" : "=l"(r) : "l"(a), "l"(b), "l"(c)); return r;
}
__device__ __forceinline__ u64 add2(u64 a, u64 b){
  u64 r; asm("add.rn.f32x2 %0, %1, %2;" : "=l"(r) : "l"(a), "l"(b)); return r;
}

#define NEG2 0xBF800000BF800000ULL   // {-1.f,-1.f}
#define MZ2  0x8000000080000000ULL   // {-0.f,-0.f}

// Kahan-fold of a group value g into (s, cn) with cn = -c. 4 ops.
__device__ __forceinline__ void kfold2(u64& s, u64& cn, u64 g){
  u64 y = add2(g, cn);
  u64 t = add2(s, y);
  u64 z = fma2(t, NEG2, s);     // RN(s - t)
  cn = add2(y, z);
  s = t;
}
__device__ __forceinline__ u64 kfin2(u64 s, u64 cn){ return add2(s, cn); }  // s - c

// ------------------------------------------------------------------
// scratch (static __device__, no runtime allocation)
// ------------------------------------------------------------------
__device__ float g_f1[16*NV1];
__device__ float g_f2[32*NV2];
__device__ float g_f3[64*NV3];
__device__ float g_p1[32*NV1];
__device__ float g_p2[32*NV2];
__device__ float g_p3[32*NV3];
__device__ float g_s1[NV1];
__device__ float g_s2[NV2];
__device__ float g_s3[NV3];
__device__ float g_c1t[432];      // [k27][o16]
__device__ float g_c2t[13824];    // [k27][ci16][o32]
__device__ float g_c3t[55296];    // [k27][ci32][o64]
__device__ float g_l1t[512];      // [ci16][c32]
__device__ float g_l2t[1024];     // [ci32][c32]
__device__ float g_l3t[2048];     // [ci64][c32]
__device__ unsigned g_hist16[3][65536];
__device__ unsigned g_hist8[3][256];
__device__ int g_ctrl[3][8];
__device__ unsigned g_candKey[3][CAP];
__device__ unsigned g_candIdx[3][CAP];
__device__ float g_topval[3*K_TOP];
__device__ unsigned g_topidx[3*K_TOP];

// ------------------------------------------------------------------
__global__ void prep_k(const float* __restrict__ c1w, const float* __restrict__ c2w,
                       const float* __restrict__ c3w, const float* __restrict__ l1w,
                       const float* __restrict__ l2w, const float* __restrict__ l3w){
  int t = blockIdx.x*blockDim.x + threadIdx.x;
  if (t < 432){ int k=t/16, o=t%16; g_c1t[t] = c1w[o*27+k]; }
  if (t < 13824){ int k=t/512; int ci=(t>>5)&15; int o=t&31; g_c2t[t]=c2w[(o*16+ci)*27+k]; }
  if (t < 55296){ int k=t/2048; int ci=(t>>6)&31; int o=t&63; g_c3t[t]=c3w[(o*32+ci)*27+k]; }
  if (t < 512){ int ci=t/32, c=t%32; g_l1t[t]=l1w[c*16+ci]; }
  if (t < 1024){ int ci=t/32, c=t%32; g_l2t[t]=l2w[c*32+ci]; }
  if (t < 2048){ int ci=t/32, c=t%32; g_l3t[t]=l3w[c*64+ci]; }
}

// ------------------------------------------------------------------
// conv1: [1,96,192,192] -> relu -> f1 [16,48,96,96], 3x3x3 s2 SAME
// grouped Kahan over taps (7 groups of 4, tap 27 zero-padded)
// ------------------------------------------------------------------
__global__ void conv1_k(const float* __restrict__ x, const float* __restrict__ b){
  __shared__ float ws[448];    // [k28][o16], taps 27 padded with zeros
  __shared__ float bs[16];
  int tid = threadIdx.x;
  if (tid < 108) ((float4*)ws)[tid] = ((const float4*)g_c1t)[tid];
  if (tid >= 108 && tid < 112) ((float4*)ws)[tid] = make_float4(0.f,0.f,0.f,0.f);
  if (tid < 16) bs[tid] = b[tid];
  __syncthreads();
  const u64* wsu = (const u64*)ws;
  int v = blockIdx.x*256 + tid;
  int z = v / (H1*W1); int r = v % (H1*W1); int y = r / W1; int xx = r % W1;
  u64 S[8], C[8];
#pragma unroll
  for (int j=0;j<8;j++){ S[j]=0ULL; C[j]=MZ2; }
#pragma unroll
  for (int kk=0;kk<28;kk+=4){
    u64 in[4];
#pragma unroll
    for (int q=0;q<4;q++){
      int k=kk+q;
      float val=0.f;
      if (k<27){
        int kd=k/9, kh=(k%9)/3, kw=k%3;
        int iz=2*z+kd, iy=2*y+kh, ix=2*xx+kw;
        if (iz<96 && iy<192 && ix<192) val=__ldg(&x[(iz*192+iy)*192+ix]);
      }
      in[q]=bcast2(val);
    }
#pragma unroll
    for (int j=0;j<8;j++){
      u64 g = fma2(in[0], wsu[(kk  )*8+j], MZ2);
      g = fma2(in[1], wsu[(kk+1)*8+j], g);
      g = fma2(in[2], wsu[(kk+2)*8+j], g);
      g = fma2(in[3], wsu[(kk+3)*8+j], g);
      kfold2(S[j],C[j],g);
    }
  }
#pragma unroll
  for (int j=0;j<8;j++){
    float v0,v1; unpack2(kfin2(S[j],C[j]),v0,v1);
    g_f1[(2*j  )*NV1+v] = fmaxf(__fadd_rn(v0,bs[2*j  ]),0.f);
    g_f1[(2*j+1)*NV1+v] = fmaxf(__fadd_rn(v1,bs[2*j+1]),0.f);
  }
}

// ------------------------------------------------------------------
// conv2: f1 -> relu -> f2; 2-way oc split (16 oc/block);
// grouped Kahan over ci (4 groups of 4). Accumulation per output
// bit-identical to the 4-way split version.
// ------------------------------------------------------------------
__global__ void __launch_bounds__(256,3) conv2_k(const float* __restrict__ b){
  __shared__ float ws[6912];   // [k27][ci16][o16]
  int s = blockIdx.y;          // oc split 0..1
  int tid=threadIdx.x;
  for(int i=tid;i<6912;i+=256){
    int k=i>>8; int rr=i&255; int ci=rr>>4; int oo=rr&15;
    ws[i]=g_c2t[k*512+ci*32+s*16+oo];
  }
  __syncthreads();
  const u64* wsu = (const u64*)ws;
  int v = blockIdx.x*256+tid;
  int z=v/(H2*W2); int r=v%(H2*W2); int y=r/W2; int xx=r%W2;
  u64 S[8], C[8];
#pragma unroll
  for(int j=0;j<8;j++){ S[j]=0ULL; C[j]=MZ2; }
#pragma unroll
  for(int kd=0;kd<3;kd++){
    int iz=2*z+kd; bool okz=iz<D1;
#pragma unroll
    for(int kh=0;kh<3;kh++){
      int iy=2*y+kh; bool oky=iy<H1;
#pragma unroll
      for(int kw=0;kw<3;kw++){
        int ix=2*xx+kw;
        if(okz && oky && ix<W1){
          int off=(iz*H1+iy)*W1+ix;
          int kl=(kd*3+kh)*3+kw;
          const u64* wk=&wsu[kl*128];
#pragma unroll
          for(int cg=0;cg<4;cg++){
            int ci0=cg*4;
            u64 in0=bcast2(__ldg(&g_f1[(ci0  )*NV1+off]));
            u64 in1=bcast2(__ldg(&g_f1[(ci0+1)*NV1+off]));
            u64 in2=bcast2(__ldg(&g_f1[(ci0+2)*NV1+off]));
            u64 in3=bcast2(__ldg(&g_f1[(ci0+3)*NV1+off]));
#pragma unroll
            for(int j=0;j<8;j++){
              u64 g = fma2(in0, wk[(ci0  )*8+j], MZ2);
              g = fma2(in1, wk[(ci0+1)*8+j], g);
              g = fma2(in2, wk[(ci0+2)*8+j], g);
              g = fma2(in3, wk[(ci0+3)*8+j], g);
              kfold2(S[j],C[j],g);
            }
          }
        }
      }
    }
  }
#pragma unroll
  for(int j=0;j<8;j++){
    float v0,v1; unpack2(kfin2(S[j],C[j]),v0,v1);
    int c=s*16+2*j;
    g_f2[c*NV2+v]    =fmaxf(__fadd_rn(v0,__ldg(&b[c])),0.f);
    g_f2[(c+1)*NV2+v]=fmaxf(__fadd_rn(v1,__ldg(&b[c+1])),0.f);
  }
}

// ------------------------------------------------------------------
// conv3: f2 -> relu -> f3; balanced warp layout; grouped Kahan (8x4 ci)
// ------------------------------------------------------------------
__global__ void conv3_k(const float* __restrict__ b){
  __shared__ float ws[8192];    // 4 taps * 32ci * 64oc
  __shared__ float shin[7200];  // 32ci * 5*5*9
  int tid=threadIdx.x;          // 256 threads
  int bt=blockIdx.x;
  int btz=bt/72; int rem=bt%72; int bty=rem/6; int btx=rem%6;
  int og = ((tid>>2)&7) | (((tid>>5)&1)<<3);   // 0..15 (4 oc each)
  int vi = (tid&3) | (((tid>>6)&3)<<2);        // 0..15
  int vz=vi>>3; int vy=(vi>>2)&1; int vx=vi&3;
  int z0=btz*4, y0=bty*4, x0=btx*8;
  for(int i=tid;i<7200;i+=256){
    int cl=i/225; int r=i%225; int lz=r/45; int r2=r%45; int ly=r2/9; int lx=r2%9;
    int gz=z0+lz, gy=y0+ly, gx=x0+lx;
    shin[i]=(gz<D2&&gy<H2&&gx<W2)? g_f2[cl*NV2+(gz*H2+gy)*W2+gx] : 0.f;
  }
  const u64* wsu=(const u64*)ws;
  u64 S[2]={0ULL,0ULL}, C[2]={MZ2,MZ2};
  int sbase=(2*vz)*45+(2*vy)*9+(2*vx);
  for(int ph=0; ph<7; ph++){
    int ktaps=(ph==6)?3:4;
    __syncthreads();
    for(int i=tid;i<ktaps*2048;i+=256) ws[i]=g_c3t[ph*8192+i];
    __syncthreads();
    for(int kl=0;kl<ktaps;kl++){
      int k=ph*4+kl;
      int kd=k/9, kh=(k%9)/3, kw=k%3;
      const float* sh=&shin[sbase + kd*45 + kh*9 + kw];
      const u64* wb=&wsu[kl*1024 + og*2];
#pragma unroll
      for(int cg=0;cg<8;cg++){
        int ci0=cg*4;
        u64 in0=bcast2(sh[(ci0  )*225]);
        u64 in1=bcast2(sh[(ci0+1)*225]);
        u64 in2=bcast2(sh[(ci0+2)*225]);
        u64 in3=bcast2(sh[(ci0+3)*225]);
        u64 g0 = fma2(in0, wb[(ci0  )*32], MZ2);
        u64 g1 = fma2(in0, wb[(ci0  )*32+1], MZ2);
        g0 = fma2(in1, wb[(ci0+1)*32], g0);
        g1 = fma2(in1, wb[(ci0+1)*32+1], g1);
        g0 = fma2(in2, wb[(ci0+2)*32], g0);
        g1 = fma2(in2, wb[(ci0+2)*32+1], g1);
        g0 = fma2(in3, wb[(ci0+3)*32], g0);
        g1 = fma2(in3, wb[(ci0+3)*32+1], g1);
        kfold2(S[0],C[0],g0);
        kfold2(S[1],C[1],g1);
      }
    }
  }
  int oz=btz*2+vz, oy=bty*2+vy, ox=btx*4+vx;
  int v=(oz*H3+oy)*W3+ox;
#pragma unroll
  for(int j=0;j<2;j++){
    float v0,v1; unpack2(kfin2(S[j],C[j]),v0,v1);
    int c=og*4+2*j;
    g_f3[c*NV3+v]    =fmaxf(__fadd_rn(v0,__ldg(&b[c])),0.f);
    g_f3[(c+1)*NV3+v]=fmaxf(__fadd_rn(v1,__ldg(&b[c+1])),0.f);
  }
}

// ------------------------------------------------------------------
__device__ __forceinline__ unsigned okey(float f){
  unsigned u=__float_as_uint(f);
  return (u & 0x80000000u) ? ~u : (u | 0x80000000u);
}
__device__ __forceinline__ float fromkey(unsigned k){
  unsigned u = (k & 0x80000000u) ? (k ^ 0x80000000u) : ~k;
  return __uint_as_float(u);
}

// ------------------------------------------------------------------
// FPN laterals + top-down adds + channel-max score (+ fused hist16)
// ------------------------------------------------------------------
__global__ void p3_k(const float* __restrict__ b){
  __shared__ float lw[2048];
  int tid=threadIdx.x;
  for(int i=tid;i<512;i+=256) ((float4*)lw)[i]=((const float4*)g_l3t)[i];
  __syncthreads();
  const u64* lwu=(const u64*)lw;
  int v=blockIdx.x*256+tid;
  u64 S[16], C[16];
#pragma unroll
  for(int j=0;j<16;j++){ S[j]=0ULL; C[j]=MZ2; }
#pragma unroll 4
  for(int cg=0;cg<16;cg++){
    int ci0=cg*4;
    u64 in0=bcast2(g_f3[(ci0  )*NV3+v]);
    u64 in1=bcast2(g_f3[(ci0+1)*NV3+v]);
    u64 in2=bcast2(g_f3[(ci0+2)*NV3+v]);
    u64 in3=bcast2(g_f3[(ci0+3)*NV3+v]);
#pragma unroll
    for(int j=0;j<16;j++){
      u64 g = fma2(in0, lwu[(ci0  )*16+j], MZ2);
      g = fma2(in1, lwu[(ci0+1)*16+j], g);
      g = fma2(in2, lwu[(ci0+2)*16+j], g);
      g = fma2(in3, lwu[(ci0+3)*16+j], g);
      kfold2(S[j],C[j],g);
    }
  }
  float mx=-1e30f;
#pragma unroll
  for(int j=0;j<16;j++){
    float v0,v1; unpack2(kfin2(S[j],C[j]),v0,v1);
    float p0=__fadd_rn(v0,__ldg(&b[2*j]));
    float p1=__fadd_rn(v1,__ldg(&b[2*j+1]));
    g_p3[(2*j)*NV3+v]=p0; g_p3[(2*j+1)*NV3+v]=p1;
    mx=fmaxf(mx,fmaxf(p0,p1));
  }
  g_s3[v]=mx;
  atomicAdd(&g_hist16[2][okey(mx)>>16],1u);
}

__global__ void p2_k(const float* __restrict__ b){
  __shared__ float lw[1024];
  int tid=threadIdx.x;
  if(tid<256) ((float4*)lw)[tid]=((const float4*)g_l2t)[tid];
  __syncthreads();
  const u64* lwu=(const u64*)lw;
  int v=blockIdx.x*256+tid;
  int z=v/(H2*W2); int r=v%(H2*W2); int y=r/W2; int xx=r%W2;
  int v3=((z>>1)*H3+(y>>1))*W3+(xx>>1);
  u64 S[16], C[16];
#pragma unroll
  for(int j=0;j<16;j++){ S[j]=0ULL; C[j]=MZ2; }
#pragma unroll 2
  for(int cg=0;cg<8;cg++){
    int ci0=cg*4;
    u64 in0=bcast2(g_f2[(ci0  )*NV2+v]);
    u64 in1=bcast2(g_f2[(ci0+1)*NV2+v]);
    u64 in2=bcast2(g_f2[(ci0+2)*NV2+v]);
    u64 in3=bcast2(g_f2[(ci0+3)*NV2+v]);
#pragma unroll
    for(int j=0;j<16;j++){
      u64 g = fma2(in0, lwu[(ci0  )*16+j], MZ2);
      g = fma2(in1, lwu[(ci0+1)*16+j], g);
      g = fma2(in2, lwu[(ci0+2)*16+j], g);
      g = fma2(in3, lwu[(ci0+3)*16+j], g);
      kfold2(S[j],C[j],g);
    }
  }
  float mx=-1e30f;
#pragma unroll
  for(int j=0;j<16;j++){
    float v0,v1; unpack2(kfin2(S[j],C[j]),v0,v1);
    float p0=__fadd_rn(__fadd_rn(v0,__ldg(&b[2*j])),   g_p3[(2*j)*NV3+v3]);
    float p1=__fadd_rn(__fadd_rn(v1,__ldg(&b[2*j+1])), g_p3[(2*j+1)*NV3+v3]);
    g_p2[(2*j)*NV2+v]=p0; g_p2[(2*j+1)*NV2+v]=p1;
    mx=fmaxf(mx,fmaxf(p0,p1));
  }
  g_s2[v]=mx;
  atomicAdd(&g_hist16[1][okey(mx)>>16],1u);
}

__global__ void p1_k(const float* __restrict__ b){
  __shared__ float lw[512];
  int tid=threadIdx.x;
  if(tid<128) ((float4*)lw)[tid]=((const float4*)g_l1t)[tid];
  __syncthreads();
  const u64* lwu=(const u64*)lw;
  int v=blockIdx.x*256+tid;
  int z=v/(H1*W1); int r=v%(H1*W1); int y=r/W1; int xx=r%W1;
  int v2=((z>>1)*H2+(y>>1))*W2+(xx>>1);
  u64 S[16], C[16];
#pragma unroll
  for(int j=0;j<16;j++){ S[j]=0ULL; C[j]=MZ2; }
#pragma unroll
  for(int cg=0;cg<4;cg++){
    int ci0=cg*4;
    u64 in0=bcast2(g_f1[(ci0  )*NV1+v]);
    u64 in1=bcast2(g_f1[(ci0+1)*NV1+v]);
    u64 in2=bcast2(g_f1[(ci0+2)*NV1+v]);
    u64 in3=bcast2(g_f1[(ci0+3)*NV1+v]);
#pragma unroll
    for(int j=0;j<16;j++){
      u64 g = fma2(in0, lwu[(ci0  )*16+j], MZ2);
      g = fma2(in1, lwu[(ci0+1)*16+j], g);
      g = fma2(in2, lwu[(ci0+2)*16+j], g);
      g = fma2(in3, lwu[(ci0+3)*16+j], g);
      kfold2(S[j],C[j],g);
    }
  }
  float mx=-1e30f;
#pragma unroll
  for(int j=0;j<16;j++){
    float v0,v1; unpack2(kfin2(S[j],C[j]),v0,v1);
    float p0=__fadd_rn(__fadd_rn(v0,__ldg(&b[2*j])),   g_p2[(2*j)*NV2+v2]);
    float p1=__fadd_rn(__fadd_rn(v1,__ldg(&b[2*j+1])), g_p2[(2*j+1)*NV2+v2]);
    g_p1[(2*j)*NV1+v]=p0; g_p1[(2*j+1)*NV1+v]=p1;
    mx=fmaxf(mx,fmaxf(p0,p1));
  }
  g_s1[v]=mx;
  atomicAdd(&g_hist16[0][okey(mx)>>16],1u);
}

// ------------------------------------------------------------------
// exact top-K=512 per level
// ------------------------------------------------------------------
__device__ __forceinline__ const float* level_score(int l){
  return (l==0)? g_s1 : (l==1)? g_s2 : g_s3;
}
__device__ __forceinline__ int level_n(int l){
  return (l==0)? NV1 : (l==1)? NV2 : NV3;
}

__global__ void tk_clear(){
  int t=blockIdx.x*256+threadIdx.x;
  if(t<3*65536) ((unsigned*)g_hist16)[t]=0;
  if(t<3*256) ((unsigned*)g_hist8)[t]=0;
  if(t<3*8) ((int*)g_ctrl)[t]=0;
}
__global__ void tk_find16(){
  int l=blockIdx.x;
  __shared__ unsigned part[256];
  int t=threadIdx.x;
  unsigned sm=0;
  for(int i=0;i<256;i++) sm+=g_hist16[l][t*256+i];
  part[t]=sm;
  __syncthreads();
  if(t==0){
    unsigned cum=0;
    for(int c=255;c>=0;c--){
      if(cum+part[c]>=K_TOP){
        for(int bb=c*256+255;;bb--){
          unsigned h=g_hist16[l][bb];
          if(cum+h>=K_TOP){ g_ctrl[l][0]=bb; g_ctrl[l][1]=(int)cum; break; }
          cum+=h;
        }
        break;
      }
      cum+=part[c];
    }
  }
}
__global__ void tk_hist8(){
  int l=blockIdx.y;
  int t=blockIdx.x*256+threadIdx.x; if(t>=level_n(l))return;
  unsigned k=okey(level_score(l)[t]);
  if((int)(k>>16)==g_ctrl[l][0]) atomicAdd(&g_hist8[l][(k>>8)&255],1u);
}
__global__ void tk_find8(){
  int l=threadIdx.x; if(l>=3)return;
  unsigned cum=(unsigned)g_ctrl[l][1];
  int b16=g_ctrl[l][0];
  for(int bb=255;bb>=0;bb--){
    unsigned h=g_hist8[l][bb];
    if(cum+h>=K_TOP){ g_ctrl[l][2]=(b16<<8)|bb; break; }
    cum+=h;
  }
}
__global__ void tk_gather(){
  int l=blockIdx.y;
  int t=blockIdx.x*256+threadIdx.x; if(t>=level_n(l))return;
  unsigned k=okey(level_score(l)[t]);
  if((int)(k>>8) >= g_ctrl[l][2]){
    int pos=atomicAdd(&g_ctrl[l][3],1);
    if(pos<CAP){ g_candKey[l][pos]=k; g_candIdx[l][pos]=t; }
  }
}
__global__ void tk_sort(){
  int level=blockIdx.x;
  __shared__ unsigned long long a[CAP];
  int t=threadIdx.x;
  int M=min(g_ctrl[level][3],CAP);
  for(int i=t;i<CAP;i+=1024)
    a[i] = (i<M)? ((((unsigned long long)g_candKey[level][i])<<32) | (unsigned)(~g_candIdx[level][i])) : 0ULL;
  __syncthreads();
  for(int kk=2;kk<=CAP;kk<<=1){
    for(int j=kk>>1;j>0;j>>=1){
      for(int i=t;i<CAP;i+=1024){
        int ixj=i^j;
        if(ixj>i){
          bool asc=((i&kk)!=0);
          unsigned long long A=a[i],B=a[ixj];
          if(asc? (A>B):(A<B)){ a[i]=B; a[ixj]=A; }
        }
      }
      __syncthreads();
    }
  }
  if(t<K_TOP){
    unsigned long long c=a[t];
    g_topval[level*K_TOP+t]=fromkey((unsigned)(c>>32));
    g_topidx[level*K_TOP+t]=~((unsigned)c);
  }
}

// ------------------------------------------------------------------
// per-candidate: cube mean/std (fp64, parallel gather) -> MLP -> out
// ------------------------------------------------------------------
__global__ void mlp_k(const float* __restrict__ w1,const float* __restrict__ b1,
                      const float* __restrict__ w2,const float* __restrict__ b2,
                      float* __restrict__ out){
  int l=blockIdx.y; int slot=blockIdx.x; int t=threadIdx.x;
  __shared__ float cvs[2048];    // [ch32][64]
  __shared__ double psum[128];
  __shared__ double msh[32];
  __shared__ float feat[64];
  __shared__ float h[128];
  int D,H,W; const float* p;
  if(l==0){D=D1;H=H1;W=W1;p=g_p1;}
  else if(l==1){D=D2;H=H2;W=W2;p=g_p2;}
  else {D=D3;H=H3;W=W3;p=g_p3;}
  unsigned idx=g_topidx[l*K_TOP+slot];
  float val=g_topval[l*K_TOP+slot];
  int plane=D*H*W;
  int z=(int)idx/(H*W); int r=(int)idx%(H*W); int y=r/W; int xx=r%W;
  int zs=min(max(z-2,0),D-4);
  int ys=min(max(y-2,0),H-4);
  int xs=min(max(xx-2,0),W-4);
  int ch=t>>2, part=t&3;
  {
    const float* base = p + ch*plane + ((zs+part)*H+ys)*W + xs;
    float* cvp = &cvs[ch*64 + part*16];
    double s=0.0;
#pragma unroll
    for(int dy=0;dy<4;dy++)
#pragma unroll
      for(int dx=0;dx<4;dx++){
        float vv = base[dy*W+dx];
        cvp[dy*4+dx]=vv;
        s += (double)vv;
      }
    psum[t]=s;
  }
  __syncthreads();
  if(t<32){
    double m=(((psum[t*4]+psum[t*4+1])+psum[t*4+2])+psum[t*4+3])*(1.0/64.0);
    msh[t]=m;
    feat[t]=(float)m;
  }
  __syncthreads();
  {
    double m=msh[ch];
    const float* cvp=&cvs[ch*64 + part*16];
    double ss=0.0;
#pragma unroll
    for(int k=0;k<16;k++){ double d=(double)cvp[k]-m; ss+=d*d; }
    psum[t]=ss;
  }
  __syncthreads();
  if(t<32){
    double var=(((psum[t*4]+psum[t*4+1])+psum[t*4+2])+psum[t*4+3])*(1.0/64.0);
    feat[32+t]=(float)sqrt(var+1e-6);
  }
  __syncthreads();
  {
    double acc=0.0;
    for(int i=0;i<64;i++) acc += (double)feat[i]*(double)__ldg(&w1[i*128+t]);
    h[t]=fmaxf((float)(acc+(double)__ldg(&b1[t])),0.f);
  }
  __syncthreads();
  if(t<2){
    double acc=0.0;
    for(int j=0;j<128;j++) acc+=(double)h[j]*(double)__ldg(&w2[j*2+t]);
    float valid=(val>0.5f)?1.f:0.f;
    out[(l*K_TOP+slot)*2+t]=(float)(acc+(double)__ldg(&b2[t]))*valid;
  }
}

// ------------------------------------------------------------------
extern "C" void kernel_launch(void* const* d_in, const int* in_sizes, int n_in,
                              void* d_out, int out_size){
  const float* x  =(const float*)d_in[0];
  const float* c1w=(const float*)d_in[1];  const float* c1b=(const float*)d_in[2];
  const float* c2w=(const float*)d_in[3];  const float* c2b=(const float*)d_in[4];
  const float* c3w=(const float*)d_in[5];  const float* c3b=(const float*)d_in[6];
  const float* l1w=(const float*)d_in[7];  const float* l1b=(const float*)d_in[8];
  const float* l2w=(const float*)d_in[9];  const float* l2b=(const float*)d_in[10];
  const float* l3w=(const float*)d_in[11]; const float* l3b=(const float*)d_in[12];
  const float* w1 =(const float*)d_in[13]; const float* b1 =(const float*)d_in[14];
  const float* w2 =(const float*)d_in[15]; const float* b2 =(const float*)d_in[16];
  float* out=(float*)d_out;

  prep_k<<<216,256>>>(c1w,c2w,c3w,l1w,l2w,l3w);
  tk_clear<<<768,256>>>();
  conv1_k<<<NV1/256,256>>>(x,c1b);
  conv2_k<<<dim3(NV2/256,2),256>>>(c2b);
  conv3_k<<<432,256>>>(c3b);
  p3_k<<<NV3/256,256>>>(l3b);
  p2_k<<<NV2/256,256>>>(l2b);
  p1_k<<<NV1/256,256>>>(l1b);

  int nb=(NV1+255)/256;
  tk_find16<<<3,256>>>();
  tk_hist8<<<dim3(nb,3),256>>>();
  tk_find8<<<1,32>>>();
  tk_gather<<<dim3(nb,3),256>>>();
  tk_sort<<<3,1024>>>();

  mlp_k<<<dim3(K_TOP,3),128>>>(w1,b1,w2,b2,out);
}

// round 16
// speedup vs baseline: 1.3534x; 1.2369x over previous
#include <cuda_runtime.h>
#include <math.h>

#define K_TOP 512
#define CAP 4096
#define SORTN 1024

// level dims
#define D1 48
#define H1 96
#define W1 96
#define NV1 (D1*H1*W1)   // 442368
#define D2 24
#define H2 48
#define W2 48
#define NV2 (D2*H2*W2)   // 55296
#define D3 12
#define H3 24
#define W3 24
#define NV3 (D3*H3*W3)   // 6912

typedef unsigned long long u64;

// ------------------------------------------------------------------
// packed f32x2 primitives (sm_103a FFMA2 path)
// ------------------------------------------------------------------
__device__ __forceinline__ u64 bcast2(float a){
  u64 r; asm("mov.b64 %0, {%1, %1};" : "=l"(r) : "f"(a)); return r;
}
__device__ __forceinline__ void unpack2(u64 v, float& lo, float& hi){
  asm("mov.b64 {%0, %1}, %2;" : "=f"(lo), "=f"(hi) : "l"(v));
}
__device__ __forceinline__ u64 fma2(u64 a, u64 b, u64 c){
  u64 r; asm("fma.rn.f32x2 %0, %1, %2, %3;" : "=l"(r) : "l"(a), "l"(b), "l"(c)); return r;
}
__device__ __forceinline__ u64 add2(u64 a, u64 b){
  u64 r; asm("add.rn.f32x2 %0, %1, %2;" : "=l"(r) : "l"(a), "l"(b)); return r;
}

#define NEG2 0xBF800000BF800000ULL   // {-1.f,-1.f}
#define MZ2  0x8000000080000000ULL   // {-0.f,-0.f}

// Kahan-fold of a group value g into (s, cn) with cn = -c. 4 ops.
__device__ __forceinline__ void kfold2(u64& s, u64& cn, u64 g){
  u64 y = add2(g, cn);
  u64 t = add2(s, y);
  u64 z = fma2(t, NEG2, s);     // RN(s - t)
  cn = add2(y, z);
  s = t;
}
__device__ __forceinline__ u64 kfin2(u64 s, u64 cn){ return add2(s, cn); }  // s - c

// ------------------------------------------------------------------
// scratch (static __device__, no runtime allocation)
// ------------------------------------------------------------------
__device__ float g_f1[16*NV1];
__device__ float g_f2[32*NV2];
__device__ float g_f3[64*NV3];
__device__ float g_p1[32*NV1];
__device__ float g_p2[32*NV2];
__device__ float g_p3[32*NV3];
__device__ float g_s1[NV1];
__device__ float g_s2[NV2];
__device__ float g_s3[NV3];
__device__ float g_c1t[432];      // [k27][o16]
__device__ float g_c2t[13824];    // [k27][ci16][o32]
__device__ float g_c3t[55296];    // [k27][ci32][o64]
__device__ float g_l1t[512];      // [ci16][c32]
__device__ float g_l2t[1024];     // [ci32][c32]
__device__ float g_l3t[2048];     // [ci64][c32]
__device__ unsigned g_hist16[3][65536];
__device__ unsigned g_hist8[3][256];
__device__ int g_ctrl[3][8];
__device__ unsigned g_candKey[3][CAP];
__device__ unsigned g_candIdx[3][CAP];
__device__ float g_topval[3*K_TOP];
__device__ unsigned g_topidx[3*K_TOP];

// ------------------------------------------------------------------
// weight transposition + histogram/ctrl clear (fused; once per launch)
// ------------------------------------------------------------------
__global__ void prep_k(const float* __restrict__ c1w, const float* __restrict__ c2w,
                       const float* __restrict__ c3w, const float* __restrict__ l1w,
                       const float* __restrict__ l2w, const float* __restrict__ l3w){
  int t = blockIdx.x*blockDim.x + threadIdx.x;
  if (t < 432){ int k=t/16, o=t%16; g_c1t[t] = c1w[o*27+k]; }
  if (t < 13824){ int k=t/512; int ci=(t>>5)&15; int o=t&31; g_c2t[t]=c2w[(o*16+ci)*27+k]; }
  if (t < 55296){ int k=t/2048; int ci=(t>>6)&31; int o=t&63; g_c3t[t]=c3w[(o*32+ci)*27+k]; }
  if (t < 512){ int ci=t/32, c=t%32; g_l1t[t]=l1w[c*16+ci]; }
  if (t < 1024){ int ci=t/32, c=t%32; g_l2t[t]=l2w[c*32+ci]; }
  if (t < 2048){ int ci=t/32, c=t%32; g_l3t[t]=l3w[c*64+ci]; }
  if (t < 3*65536) ((unsigned*)g_hist16)[t]=0;
  if (t < 3*256) ((unsigned*)g_hist8)[t]=0;
  if (t < 3*8) ((int*)g_ctrl)[t]=0;
}

// ------------------------------------------------------------------
// conv1: [1,96,192,192] -> relu -> f1 [16,48,96,96], 3x3x3 s2 SAME
// grouped Kahan over taps (7 groups of 4, tap 27 zero-padded)
// ------------------------------------------------------------------
__global__ void conv1_k(const float* __restrict__ x, const float* __restrict__ b){
  __shared__ float ws[448];    // [k28][o16], taps 27 padded with zeros
  __shared__ float bs[16];
  int tid = threadIdx.x;
  if (tid < 108) ((float4*)ws)[tid] = ((const float4*)g_c1t)[tid];
  if (tid >= 108 && tid < 112) ((float4*)ws)[tid] = make_float4(0.f,0.f,0.f,0.f);
  if (tid < 16) bs[tid] = b[tid];
  __syncthreads();
  const u64* wsu = (const u64*)ws;
  int v = blockIdx.x*256 + tid;
  int z = v / (H1*W1); int r = v % (H1*W1); int y = r / W1; int xx = r % W1;
  u64 S[8], C[8];
#pragma unroll
  for (int j=0;j<8;j++){ S[j]=0ULL; C[j]=MZ2; }
#pragma unroll
  for (int kk=0;kk<28;kk+=4){
    u64 in[4];
#pragma unroll
    for (int q=0;q<4;q++){
      int k=kk+q;
      float val=0.f;
      if (k<27){
        int kd=k/9, kh=(k%9)/3, kw=k%3;
        int iz=2*z+kd, iy=2*y+kh, ix=2*xx+kw;
        if (iz<96 && iy<192 && ix<192) val=__ldg(&x[(iz*192+iy)*192+ix]);
      }
      in[q]=bcast2(val);
    }
#pragma unroll
    for (int j=0;j<8;j++){
      u64 g = fma2(in[0], wsu[(kk  )*8+j], MZ2);
      g = fma2(in[1], wsu[(kk+1)*8+j], g);
      g = fma2(in[2], wsu[(kk+2)*8+j], g);
      g = fma2(in[3], wsu[(kk+3)*8+j], g);
      kfold2(S[j],C[j],g);
    }
  }
#pragma unroll
  for (int j=0;j<8;j++){
    float o0,o1; unpack2(kfin2(S[j],C[j]),o0,o1);
    g_f1[(2*j  )*NV1+v] = fmaxf(__fadd_rn(o0,bs[2*j  ]),0.f);
    g_f1[(2*j+1)*NV1+v] = fmaxf(__fadd_rn(o1,bs[2*j+1]),0.f);
  }
}

// ------------------------------------------------------------------
// conv2: f1 -> relu -> f2; 4-way oc split (8 oc) x 2 x-adjacent
// voxels per thread. Weight LDS per output halved; fold order per
// output bit-identical (taps -> cg -> j).
// ------------------------------------------------------------------
__global__ void __launch_bounds__(256,3) conv2_k(const float* __restrict__ b){
  __shared__ float ws[3456];   // [k27][ci16][o8]
  int s = blockIdx.y;          // oc split 0..3
  int tid=threadIdx.x;
  for(int i=tid;i<3456;i+=256){
    int k=i>>7; int rr=i&127; int ci=rr>>3; int oo=rr&7;
    ws[i]=g_c2t[k*512+ci*32+s*8+oo];
  }
  __syncthreads();
  const u64* wsu = (const u64*)ws;
  int v0 = blockIdx.x*512 + tid*2;     // voxel A (even); B = v0+1 (same row: W2 even)
  int z=v0/(H2*W2); int r=v0%(H2*W2); int y=r/W2; int xA=r%W2;
  u64 SA[4], CA[4], SB[4], CB[4];
#pragma unroll
  for(int j=0;j<4;j++){ SA[j]=0ULL; CA[j]=MZ2; SB[j]=0ULL; CB[j]=MZ2; }
#pragma unroll
  for(int kd=0;kd<3;kd++){
    int iz=2*z+kd; bool okz=iz<D1;
#pragma unroll
    for(int kh=0;kh<3;kh++){
      int iy=2*y+kh; bool rowok=okz&&(iy<H1);
      int rowoff=(iz*H1+iy)*W1;
#pragma unroll
      for(int kw=0;kw<3;kw++){
        int ixA=2*xA+kw;
        bool okA = rowok && (ixA<W1);
        bool okB = rowok && (ixA+2<W1);
        int kl=(kd*3+kh)*3+kw;
        const u64* wk=&wsu[kl*64];
#pragma unroll
        for(int cg=0;cg<4;cg++){
          int ci0=cg*4;
          u64 a0=0,a1=0,a2=0,a3=0,b0=0,b1=0,b2=0,b3=0;
          if(okA){
            a0=bcast2(__ldg(&g_f1[(ci0  )*NV1+rowoff+ixA]));
            a1=bcast2(__ldg(&g_f1[(ci0+1)*NV1+rowoff+ixA]));
            a2=bcast2(__ldg(&g_f1[(ci0+2)*NV1+rowoff+ixA]));
            a3=bcast2(__ldg(&g_f1[(ci0+3)*NV1+rowoff+ixA]));
          }
          if(okB){
            b0=bcast2(__ldg(&g_f1[(ci0  )*NV1+rowoff+ixA+2]));
            b1=bcast2(__ldg(&g_f1[(ci0+1)*NV1+rowoff+ixA+2]));
            b2=bcast2(__ldg(&g_f1[(ci0+2)*NV1+rowoff+ixA+2]));
            b3=bcast2(__ldg(&g_f1[(ci0+3)*NV1+rowoff+ixA+2]));
          }
#pragma unroll
          for(int j=0;j<4;j++){
            u64 w0=wk[(ci0  )*4+j];
            u64 w1=wk[(ci0+1)*4+j];
            u64 w2=wk[(ci0+2)*4+j];
            u64 w3=wk[(ci0+3)*4+j];
            if(okA){
              u64 g=fma2(a0,w0,MZ2); g=fma2(a1,w1,g); g=fma2(a2,w2,g); g=fma2(a3,w3,g);
              kfold2(SA[j],CA[j],g);
            }
            if(okB){
              u64 g=fma2(b0,w0,MZ2); g=fma2(b1,w1,g); g=fma2(b2,w2,g); g=fma2(b3,w3,g);
              kfold2(SB[j],CB[j],g);
            }
          }
        }
      }
    }
  }
#pragma unroll
  for(int j=0;j<4;j++){
    int c=s*8+2*j;
    float o0,o1;
    unpack2(kfin2(SA[j],CA[j]),o0,o1);
    g_f2[c*NV2+v0]     = fmaxf(__fadd_rn(o0,__ldg(&b[c])),0.f);
    g_f2[(c+1)*NV2+v0] = fmaxf(__fadd_rn(o1,__ldg(&b[c+1])),0.f);
    unpack2(kfin2(SB[j],CB[j]),o0,o1);
    g_f2[c*NV2+v0+1]     = fmaxf(__fadd_rn(o0,__ldg(&b[c])),0.f);
    g_f2[(c+1)*NV2+v0+1] = fmaxf(__fadd_rn(o1,__ldg(&b[c+1])),0.f);
  }
}

// ------------------------------------------------------------------
// conv3: f2 -> relu -> f3; balanced warp layout; grouped Kahan (8x4 ci)
// ------------------------------------------------------------------
__global__ void conv3_k(const float* __restrict__ b){
  __shared__ float ws[8192];    // 4 taps * 32ci * 64oc
  __shared__ float shin[7200];  // 32ci * 5*5*9
  int tid=threadIdx.x;          // 256 threads
  int bt=blockIdx.x;
  int btz=bt/72; int rem=bt%72; int bty=rem/6; int btx=rem%6;
  int og = ((tid>>2)&7) | (((tid>>5)&1)<<3);   // 0..15 (4 oc each)
  int vi = (tid&3) | (((tid>>6)&3)<<2);        // 0..15
  int vz=vi>>3; int vy=(vi>>2)&1; int vx=vi&3;
  int z0=btz*4, y0=bty*4, x0=btx*8;
  for(int i=tid;i<7200;i+=256){
    int cl=i/225; int r=i%225; int lz=r/45; int r2=r%45; int ly=r2/9; int lx=r2%9;
    int gz=z0+lz, gy=y0+ly, gx=x0+lx;
    shin[i]=(gz<D2&&gy<H2&&gx<W2)? g_f2[cl*NV2+(gz*H2+gy)*W2+gx] : 0.f;
  }
  const u64* wsu=(const u64*)ws;
  u64 S[2]={0ULL,0ULL}, C[2]={MZ2,MZ2};
  int sbase=(2*vz)*45+(2*vy)*9+(2*vx);
  for(int ph=0; ph<7; ph++){
    int ktaps=(ph==6)?3:4;
    __syncthreads();
    for(int i=tid;i<ktaps*2048;i+=256) ws[i]=g_c3t[ph*8192+i];
    __syncthreads();
    for(int kl=0;kl<ktaps;kl++){
      int k=ph*4+kl;
      int kd=k/9, kh=(k%9)/3, kw=k%3;
      const float* sh=&shin[sbase + kd*45 + kh*9 + kw];
      const u64* wb=&wsu[kl*1024 + og*2];
#pragma unroll
      for(int cg=0;cg<8;cg++){
        int ci0=cg*4;
        u64 in0=bcast2(sh[(ci0  )*225]);
        u64 in1=bcast2(sh[(ci0+1)*225]);
        u64 in2=bcast2(sh[(ci0+2)*225]);
        u64 in3=bcast2(sh[(ci0+3)*225]);
        u64 g0 = fma2(in0, wb[(ci0  )*32], MZ2);
        u64 g1 = fma2(in0, wb[(ci0  )*32+1], MZ2);
        g0 = fma2(in1, wb[(ci0+1)*32], g0);
        g1 = fma2(in1, wb[(ci0+1)*32+1], g1);
        g0 = fma2(in2, wb[(ci0+2)*32], g0);
        g1 = fma2(in2, wb[(ci0+2)*32+1], g1);
        g0 = fma2(in3, wb[(ci0+3)*32], g0);
        g1 = fma2(in3, wb[(ci0+3)*32+1], g1);
        kfold2(S[0],C[0],g0);
        kfold2(S[1],C[1],g1);
      }
    }
  }
  int oz=btz*2+vz, oy=bty*2+vy, ox=btx*4+vx;
  int v=(oz*H3+oy)*W3+ox;
#pragma unroll
  for(int j=0;j<2;j++){
    float o0,o1; unpack2(kfin2(S[j],C[j]),o0,o1);
    int c=og*4+2*j;
    g_f3[c*NV3+v]    =fmaxf(__fadd_rn(o0,__ldg(&b[c])),0.f);
    g_f3[(c+1)*NV3+v]=fmaxf(__fadd_rn(o1,__ldg(&b[c+1])),0.f);
  }
}

// ------------------------------------------------------------------
__device__ __forceinline__ unsigned okey(float f){
  unsigned u=__float_as_uint(f);
  return (u & 0x80000000u) ? ~u : (u | 0x80000000u);
}
__device__ __forceinline__ float fromkey(unsigned k){
  unsigned u = (k & 0x80000000u) ? (k ^ 0x80000000u) : ~k;
  return __uint_as_float(u);
}

// ------------------------------------------------------------------
// FPN laterals + top-down adds + channel-max score (+ fused hist16)
// ------------------------------------------------------------------
__global__ void p3_k(const float* __restrict__ b){
  __shared__ float lw[2048];
  int tid=threadIdx.x;
  for(int i=tid;i<512;i+=256) ((float4*)lw)[i]=((const float4*)g_l3t)[i];
  __syncthreads();
  const u64* lwu=(const u64*)lw;
  int v=blockIdx.x*256+tid;
  u64 S[16], C[16];
#pragma unroll
  for(int j=0;j<16;j++){ S[j]=0ULL; C[j]=MZ2; }
#pragma unroll 4
  for(int cg=0;cg<16;cg++){
    int ci0=cg*4;
    u64 in0=bcast2(g_f3[(ci0  )*NV3+v]);
    u64 in1=bcast2(g_f3[(ci0+1)*NV3+v]);
    u64 in2=bcast2(g_f3[(ci0+2)*NV3+v]);
    u64 in3=bcast2(g_f3[(ci0+3)*NV3+v]);
#pragma unroll
    for(int j=0;j<16;j++){
      u64 g = fma2(in0, lwu[(ci0  )*16+j], MZ2);
      g = fma2(in1, lwu[(ci0+1)*16+j], g);
      g = fma2(in2, lwu[(ci0+2)*16+j], g);
      g = fma2(in3, lwu[(ci0+3)*16+j], g);
      kfold2(S[j],C[j],g);
    }
  }
  float mx=-1e30f;
#pragma unroll
  for(int j=0;j<16;j++){
    float o0,o1; unpack2(kfin2(S[j],C[j]),o0,o1);
    float p0=__fadd_rn(o0,__ldg(&b[2*j]));
    float p1=__fadd_rn(o1,__ldg(&b[2*j+1]));
    g_p3[(2*j)*NV3+v]=p0; g_p3[(2*j+1)*NV3+v]=p1;
    mx=fmaxf(mx,fmaxf(p0,p1));
  }
  g_s3[v]=mx;
  atomicAdd(&g_hist16[2][okey(mx)>>16],1u);
}

__global__ void p2_k(const float* __restrict__ b){
  __shared__ float lw[1024];
  int tid=threadIdx.x;
  if(tid<256) ((float4*)lw)[tid]=((const float4*)g_l2t)[tid];
  __syncthreads();
  const u64* lwu=(const u64*)lw;
  int v=blockIdx.x*256+tid;
  int z=v/(H2*W2); int r=v%(H2*W2); int y=r/W2; int xx=r%W2;
  int v3=((z>>1)*H3+(y>>1))*W3+(xx>>1);
  u64 S[16], C[16];
#pragma unroll
  for(int j=0;j<16;j++){ S[j]=0ULL; C[j]=MZ2; }
#pragma unroll 2
  for(int cg=0;cg<8;cg++){
    int ci0=cg*4;
    u64 in0=bcast2(g_f2[(ci0  )*NV2+v]);
    u64 in1=bcast2(g_f2[(ci0+1)*NV2+v]);
    u64 in2=bcast2(g_f2[(ci0+2)*NV2+v]);
    u64 in3=bcast2(g_f2[(ci0+3)*NV2+v]);
#pragma unroll
    for(int j=0;j<16;j++){
      u64 g = fma2(in0, lwu[(ci0  )*16+j], MZ2);
      g = fma2(in1, lwu[(ci0+1)*16+j], g);
      g = fma2(in2, lwu[(ci0+2)*16+j], g);
      g = fma2(in3, lwu[(ci0+3)*16+j], g);
      kfold2(S[j],C[j],g);
    }
  }
  float mx=-1e30f;
#pragma unroll
  for(int j=0;j<16;j++){
    float o0,o1; unpack2(kfin2(S[j],C[j]),o0,o1);
    float p0=__fadd_rn(__fadd_rn(o0,__ldg(&b[2*j])),   g_p3[(2*j)*NV3+v3]);
    float p1=__fadd_rn(__fadd_rn(o1,__ldg(&b[2*j+1])), g_p3[(2*j+1)*NV3+v3]);
    g_p2[(2*j)*NV2+v]=p0; g_p2[(2*j+1)*NV2+v]=p1;
    mx=fmaxf(mx,fmaxf(p0,p1));
  }
  g_s2[v]=mx;
  atomicAdd(&g_hist16[1][okey(mx)>>16],1u);
}

__global__ void p1_k(const float* __restrict__ b){
  __shared__ float lw[512];
  int tid=threadIdx.x;
  if(tid<128) ((float4*)lw)[tid]=((const float4*)g_l1t)[tid];
  __syncthreads();
  const u64* lwu=(const u64*)lw;
  int v=blockIdx.x*256+tid;
  int z=v/(H1*W1); int r=v%(H1*W1); int y=r/W1; int xx=r%W1;
  int v2=((z>>1)*H2+(y>>1))*W2+(xx>>1);
  u64 S[16], C[16];
#pragma unroll
  for(int j=0;j<16;j++){ S[j]=0ULL; C[j]=MZ2; }
#pragma unroll
  for(int cg=0;cg<4;cg++){
    int ci0=cg*4;
    u64 in0=bcast2(g_f1[(ci0  )*NV1+v]);
    u64 in1=bcast2(g_f1[(ci0+1)*NV1+v]);
    u64 in2=bcast2(g_f1[(ci0+2)*NV1+v]);
    u64 in3=bcast2(g_f1[(ci0+3)*NV1+v]);
#pragma unroll
    for(int j=0;j<16;j++){
      u64 g = fma2(in0, lwu[(ci0  )*16+j], MZ2);
      g = fma2(in1, lwu[(ci0+1)*16+j], g);
      g = fma2(in2, lwu[(ci0+2)*16+j], g);
      g = fma2(in3, lwu[(ci0+3)*16+j], g);
      kfold2(S[j],C[j],g);
    }
  }
  float mx=-1e30f;
#pragma unroll
  for(int j=0;j<16;j++){
    float o0,o1; unpack2(kfin2(S[j],C[j]),o0,o1);
    float p0=__fadd_rn(__fadd_rn(o0,__ldg(&b[2*j])),   g_p2[(2*j)*NV2+v2]);
    float p1=__fadd_rn(__fadd_rn(o1,__ldg(&b[2*j+1])), g_p2[(2*j+1)*NV2+v2]);
    g_p1[(2*j)*NV1+v]=p0; g_p1[(2*j+1)*NV1+v]=p1;
    mx=fmaxf(mx,fmaxf(p0,p1));
  }
  g_s1[v]=mx;
  atomicAdd(&g_hist16[0][okey(mx)>>16],1u);
}

// ------------------------------------------------------------------
// exact top-K=512 per level
// ------------------------------------------------------------------
__device__ __forceinline__ const float* level_score(int l){
  return (l==0)? g_s1 : (l==1)? g_s2 : g_s3;
}
__device__ __forceinline__ int level_n(int l){
  return (l==0)? NV1 : (l==1)? NV2 : NV3;
}

__global__ void tk_find16(){
  int l=blockIdx.x;
  __shared__ unsigned part[256];
  int t=threadIdx.x;
  unsigned sm=0;
  for(int i=0;i<256;i++) sm+=g_hist16[l][t*256+i];
  part[t]=sm;
  __syncthreads();
  if(t==0){
    unsigned cum=0;
    for(int c=255;c>=0;c--){
      if(cum+part[c]>=K_TOP){
        for(int bb=c*256+255;;bb--){
          unsigned h=g_hist16[l][bb];
          if(cum+h>=K_TOP){ g_ctrl[l][0]=bb; g_ctrl[l][1]=(int)cum; break; }
          cum+=h;
        }
        break;
      }
      cum+=part[c];
    }
  }
}
__global__ void tk_hist8(){
  int l=blockIdx.y;
  int t=blockIdx.x*256+threadIdx.x; if(t>=level_n(l))return;
  unsigned k=okey(level_score(l)[t]);
  if((int)(k>>16)==g_ctrl[l][0]) atomicAdd(&g_hist8[l][(k>>8)&255],1u);
}
__global__ void tk_find8(){
  int l=threadIdx.x; if(l>=3)return;
  unsigned cum=(unsigned)g_ctrl[l][1];
  int b16=g_ctrl[l][0];
  for(int bb=255;bb>=0;bb--){
    unsigned h=g_hist8[l][bb];
    if(cum+h>=K_TOP){ g_ctrl[l][2]=(b16<<8)|bb; break; }
    cum+=h;
  }
}
__global__ void tk_gather(){
  int l=blockIdx.y;
  int t=blockIdx.x*256+threadIdx.x; if(t>=level_n(l))return;
  unsigned k=okey(level_score(l)[t]);
  if((int)(k>>8) >= g_ctrl[l][2]){
    int pos=atomicAdd(&g_ctrl[l][3],1);
    if(pos<CAP){ g_candKey[l][pos]=k; g_candIdx[l][pos]=t; }
  }
}
__global__ void tk_sort(){
  int level=blockIdx.x;
  __shared__ unsigned long long a[SORTN];
  int t=threadIdx.x;
  int M=min(g_ctrl[level][3],SORTN);
  a[t] = (t<M)? ((((unsigned long long)g_candKey[level][t])<<32) | (unsigned)(~g_candIdx[level][t])) : 0ULL;
  __syncthreads();
  for(int kk=2;kk<=SORTN;kk<<=1){
    for(int j=kk>>1;j>0;j>>=1){
      int ixj=t^j;
      if(ixj>t){
        bool asc=((t&kk)!=0);
        unsigned long long A=a[t],B=a[ixj];
        if(asc? (A>B):(A<B)){ a[t]=B; a[ixj]=A; }
      }
      __syncthreads();
    }
  }
  if(t<K_TOP){
    unsigned long long c=a[t];
    g_topval[level*K_TOP+t]=fromkey((unsigned)(c>>32));
    g_topidx[level*K_TOP+t]=~((unsigned)c);
  }
}

// ------------------------------------------------------------------
// per-candidate: cube mean/std (fp64, parallel gather) -> MLP (fp32) -> out
// ------------------------------------------------------------------
__global__ void mlp_k(const float* __restrict__ w1,const float* __restrict__ b1,
                      const float* __restrict__ w2,const float* __restrict__ b2,
                      float* __restrict__ out){
  int l=blockIdx.y; int slot=blockIdx.x; int t=threadIdx.x;
  __shared__ float cvs[2048];    // [ch32][64]
  __shared__ double psum[128];
  __shared__ double msh[32];
  __shared__ float feat[64];
  __shared__ float h[128];
  int D,H,W; const float* p;
  if(l==0){D=D1;H=H1;W=W1;p=g_p1;}
  else if(l==1){D=D2;H=H2;W=W2;p=g_p2;}
  else {D=D3;H=H3;W=W3;p=g_p3;}
  unsigned idx=g_topidx[l*K_TOP+slot];
  float val=g_topval[l*K_TOP+slot];
  int plane=D*H*W;
  int z=(int)idx/(H*W); int r=(int)idx%(H*W); int y=r/W; int xx=r%W;
  int zs=min(max(z-2,0),D-4);
  int ys=min(max(y-2,0),H-4);
  int xs=min(max(xx-2,0),W-4);
  int ch=t>>2, part=t&3;
  {
    const float* base = p + ch*plane + ((zs+part)*H+ys)*W + xs;
    float* cvp = &cvs[ch*64 + part*16];
    double s=0.0;
#pragma unroll
    for(int dy=0;dy<4;dy++)
#pragma unroll
      for(int dx=0;dx<4;dx++){
        float vv = base[dy*W+dx];
        cvp[dy*4+dx]=vv;
        s += (double)vv;
      }
    psum[t]=s;
  }
  __syncthreads();
  if(t<32){
    double m=(((psum[t*4]+psum[t*4+1])+psum[t*4+2])+psum[t*4+3])*(1.0/64.0);
    msh[t]=m;
    feat[t]=(float)m;
  }
  __syncthreads();
  {
    double m=msh[ch];
    const float* cvp=&cvs[ch*64 + part*16];
    double ss=0.0;
#pragma unroll
    for(int k=0;k<16;k++){ double d=(double)cvp[k]-m; ss+=d*d; }
    psum[t]=ss;
  }
  __syncthreads();
  if(t<32){
    double var=(((psum[t*4]+psum[t*4+1])+psum[t*4+2])+psum[t*4+3])*(1.0/64.0);
    feat[32+t]=(float)sqrt(var+1e-6);
  }
  __syncthreads();
  {
    float acc=0.f;
#pragma unroll 8
    for(int i=0;i<64;i++) acc=__fmaf_rn(feat[i], __ldg(&w1[i*128+t]), acc);
    h[t]=fmaxf(__fadd_rn(acc,__ldg(&b1[t])),0.f);
  }
  __syncthreads();
  if(t<2){
    float acc=0.f;
#pragma unroll 8
    for(int j=0;j<128;j++) acc=__fmaf_rn(h[j], __ldg(&w2[j*2+t]), acc);
    float valid=(val>0.5f)?1.f:0.f;
    out[(l*K_TOP+slot)*2+t]=__fadd_rn(acc,__ldg(&b2[t]))*valid;
  }
}

// ------------------------------------------------------------------
extern "C" void kernel_launch(void* const* d_in, const int* in_sizes, int n_in,
                              void* d_out, int out_size){
  const float* x  =(const float*)d_in[0];
  const float* c1w=(const float*)d_in[1];  const float* c1b=(const float*)d_in[2];
  const float* c2w=(const float*)d_in[3];  const float* c2b=(const float*)d_in[4];
  const float* c3w=(const float*)d_in[5];  const float* c3b=(const float*)d_in[6];
  const float* l1w=(const float*)d_in[7];  const float* l1b=(const float*)d_in[8];
  const float* l2w=(const float*)d_in[9];  const float* l2b=(const float*)d_in[10];
  const float* l3w=(const float*)d_in[11]; const float* l3b=(const float*)d_in[12];
  const float* w1 =(const float*)d_in[13]; const float* b1 =(const float*)d_in[14];
  const float* w2 =(const float*)d_in[15]; const float* b2 =(const float*)d_in[16];
  float* out=(float*)d_out;

  prep_k<<<768,256>>>(c1w,c2w,c3w,l1w,l2w,l3w);
  conv1_k<<<NV1/256,256>>>(x,c1b);
  conv2_k<<<dim3(NV2/512,4),256>>>(c2b);
  conv3_k<<<432,256>>>(c3b);
  p3_k<<<NV3/256,256>>>(l3b);
  p2_k<<<NV2/256,256>>>(l2b);
  p1_k<<<NV1/256,256>>>(l1b);

  int nb=(NV1+255)/256;
  tk_find16<<<3,256>>>();
  tk_hist8<<<dim3(nb,3),256>>>();
  tk_find8<<<1,32>>>();
  tk_gather<<<dim3(nb,3),256>>>();
  tk_sort<<<3,SORTN>>>();

  mlp_k<<<dim3(K_TOP,3),128>>>(w1,b1,w2,b2,out);
}